// round 3
// baseline (speedup 1.0000x reference)
#include <cuda_runtime.h>
#include <math.h>
#include <float.h>

#define B_      32
#define L_      2048
#define D_      1024
#define P_      1024
#define TOPK_   5
#define ALPHA_  0.1f
#define EPS_    1e-12f
#define LSPLIT  16
#define D4      (D_/4)            // 256 float4 per row

// deterministic scratch (no atomics, no allocation)
__device__ float g_partial[B_ * LSPLIT * D_];   // per-(batch, lsplit) partial sums
__device__ float g_agg[B_ * D_];                // alpha * proto_agg, per batch

// ---------------------------------------------------------------------------
// Kernel 1: partial sums over L.  grid = (B_, LSPLIT), block = 256 threads.
// Each block reduces 128 rows of D=1024 floats (one float4 column per thread).
// ---------------------------------------------------------------------------
__global__ __launch_bounds__(256) void mean_kernel(const float* __restrict__ x) {
    const int b = blockIdx.x;
    const int s = blockIdx.y;
    const int t = threadIdx.x;
    const int rows = L_ / LSPLIT;   // 128

    const float4* xp = (const float4*)(x + ((long long)b * L_ + (long long)s * rows) * D_);
    float4 acc = make_float4(0.f, 0.f, 0.f, 0.f);

#pragma unroll 8
    for (int l = 0; l < rows; ++l) {
        float4 v = xp[(long long)l * D4 + t];
        acc.x += v.x; acc.y += v.y; acc.z += v.z; acc.w += v.w;
    }
    float4* gp = (float4*)g_partial;
    gp[(b * LSPLIT + s) * D4 + t] = acc;
}

// ---------------------------------------------------------------------------
// Kernel 2: per-batch scores + top-5 + softmax + weighted prototype agg.
// grid = B_ blocks, 256 threads (8 warps).
// ---------------------------------------------------------------------------
__global__ __launch_bounds__(256) void score_kernel(const float* __restrict__ protos) {
    __shared__ float qs[D_];        // normalized query
    __shared__ float scores[P_];
    __shared__ float red_v[256];
    __shared__ int   red_i[256];
    __shared__ float topv[TOPK_];
    __shared__ int   topi[TOPK_];

    const int b = blockIdx.x;
    const int t = threadIdx.x;
    const int lane = t & 31;
    const int wid  = t >> 5;

    // --- gather query = sum of partials (fixed order => deterministic)
    float4 q = make_float4(0.f, 0.f, 0.f, 0.f);
    const float4* gp = (const float4*)g_partial;
#pragma unroll
    for (int s = 0; s < LSPLIT; ++s) {
        float4 v = gp[(b * LSPLIT + s) * D4 + t];
        q.x += v.x; q.y += v.y; q.z += v.z; q.w += v.w;
    }
    const float invL = 1.0f / (float)L_;
    q.x *= invL; q.y *= invL; q.z *= invL; q.w *= invL;

    // block-reduce sum of squares
    float ss = q.x*q.x + q.y*q.y + q.z*q.z + q.w*q.w;
    red_v[t] = ss; __syncthreads();
    for (int s = 128; s > 0; s >>= 1) {
        if (t < s) red_v[t] += red_v[t + s];
        __syncthreads();
    }
    const float qinv = 1.0f / fmaxf(sqrtf(red_v[0]), EPS_);
    __syncthreads();

    ((float4*)qs)[t] = make_float4(q.x*qinv, q.y*qinv, q.z*qinv, q.w*qinv);
    __syncthreads();

    // --- cosine scores: warp w handles prototypes w, w+8, ...
    const float4* q4 = (const float4*)qs;
    for (int p = wid; p < P_; p += 8) {
        const float4* pr = (const float4*)(protos + (long long)p * D_);
        float dot = 0.f, sq = 0.f;
#pragma unroll
        for (int j = 0; j < 8; ++j) {
            float4 pv = pr[lane + j * 32];
            float4 qv = q4[lane + j * 32];
            dot += pv.x*qv.x + pv.y*qv.y + pv.z*qv.z + pv.w*qv.w;
            sq  += pv.x*pv.x + pv.y*pv.y + pv.z*pv.z + pv.w*pv.w;
        }
#pragma unroll
        for (int o = 16; o > 0; o >>= 1) {
            dot += __shfl_xor_sync(0xFFFFFFFFu, dot, o);
            sq  += __shfl_xor_sync(0xFFFFFFFFu, sq,  o);
        }
        if (lane == 0)
            scores[p] = dot / fmaxf(sqrtf(sq), EPS_);
    }
    __syncthreads();

    // --- top-5 via 5 block-parallel argmax passes (lower index wins ties)
    for (int k = 0; k < TOPK_; ++k) {
        float bv = -FLT_MAX; int bi = P_;
#pragma unroll
        for (int j = 0; j < 4; ++j) {
            int idx = t + j * 256;
            float v = scores[idx];
            if (v > bv || (v == bv && idx < bi)) { bv = v; bi = idx; }
        }
        red_v[t] = bv; red_i[t] = bi; __syncthreads();
        for (int s = 128; s > 0; s >>= 1) {
            if (t < s) {
                float ov = red_v[t + s]; int oi = red_i[t + s];
                if (ov > red_v[t] || (ov == red_v[t] && oi < red_i[t])) {
                    red_v[t] = ov; red_i[t] = oi;
                }
            }
            __syncthreads();
        }
        if (t == 0) {
            topv[k] = red_v[0];
            topi[k] = red_i[0];
            scores[red_i[0]] = -FLT_MAX;   // exclude for next pass
        }
        __syncthreads();
    }

    // --- softmax weights (redundant per-thread) folded with ALPHA
    float m = topv[0];
#pragma unroll
    for (int k = 1; k < TOPK_; ++k) m = fmaxf(m, topv[k]);
    float e[TOPK_]; float esum = 0.f;
#pragma unroll
    for (int k = 0; k < TOPK_; ++k) { e[k] = __expf(topv[k] - m); esum += e[k]; }
    const float wsc = ALPHA_ / esum;

    // --- weighted prototype aggregate (un-normalized prototypes)
    float4 acc = make_float4(0.f, 0.f, 0.f, 0.f);
#pragma unroll
    for (int k = 0; k < TOPK_; ++k) {
        const float4* pr = (const float4*)(protos + (long long)topi[k] * D_);
        float4 pv = pr[t];
        float w = e[k] * wsc;
        acc.x += w * pv.x; acc.y += w * pv.y; acc.z += w * pv.z; acc.w += w * pv.w;
    }
    ((float4*)g_agg)[b * D4 + t] = acc;
}

// ---------------------------------------------------------------------------
// Kernel 3: out = x + agg[b] (broadcast).  float4 streaming, 4 items/thread.
// Blocks are mapped in REVERSE so first-scheduled blocks read the tail of x,
// which is still L2-resident from mean_kernel (~100 MiB of L2 hits, and DRAM
// -- not LTS -- is the binding cap at NAT clocks, so hits are real savings).
// Output stores use .cs (streaming/evict-first) to protect that residency.
//
// Each block covers 1024 consecutive float4 = 4096 floats = 4 rows of one
// batch, so the whole block shares one agg row (per-batch float4 = 2^19,
// chunk*1024 never straddles a batch boundary).
// ---------------------------------------------------------------------------
__global__ __launch_bounds__(256) void add_kernel(const float4* __restrict__ x,
                                                  float4* __restrict__ out) {
    const float4* agg = (const float4*)g_agg;
    // reversed chunk mapping
    const int chunk = gridDim.x - 1 - blockIdx.x;
    const int base  = chunk * 1024 + threadIdx.x;
    const int b     = base >> 19;          // batch for ALL 4 items of this block
    const int d4    = base & (D4 - 1);     // same dim-slot for all 4 items
    const float4 av = __ldg(&agg[(b << 8) + d4]);
#pragma unroll
    for (int k = 0; k < 4; ++k) {
        const int i = base + k * 256;
        float4 xv = x[i];
        xv.x += av.x; xv.y += av.y; xv.z += av.z; xv.w += av.w;
        __stcs(&out[i], xv);
    }
}

// ---------------------------------------------------------------------------
extern "C" void kernel_launch(void* const* d_in, const int* in_sizes, int n_in,
                              void* d_out, int out_size) {
    const float* x      = (const float*)d_in[0];   // [32, 2048, 1024]
    const float* protos = (const float*)d_in[1];   // [1024, 1024]
    float* out          = (float*)d_out;

    dim3 mgrid(B_, LSPLIT);
    mean_kernel<<<mgrid, 256>>>(x);
    score_kernel<<<B_, 256>>>(protos);

    const int total4 = B_ * L_ * D4;               // 16,777,216
    add_kernel<<<total4 / 1024, 256>>>((const float4*)x, (float4*)out);
}

// round 8
// speedup vs baseline: 2.3282x; 2.3282x over previous
#include <cuda_runtime.h>
#include <math.h>
#include <float.h>

#define B_      32
#define L_      2048
#define D_      1024
#define P_      1024
#define TOPK_   5
#define ALPHA_  0.1f
#define EPS_    1e-12f
#define LSPLIT  16
#define D4      (D_/4)            // 256 float4 per row
#define PGROUPS 16                // proto groups for score_part
#define PPG     (P_/PGROUPS)      // 64 protos per group

// deterministic scratch (no atomics, no allocation)
__device__ float g_partial[B_ * LSPLIT * D_];   // per-(batch, lsplit) partial sums
__device__ float g_query[B_ * D_];              // normalized query per batch
__device__ float g_scores[B_ * P_];             // cosine scores
__device__ float g_agg[B_ * D_];                // alpha * proto_agg, per batch

// ---------------------------------------------------------------------------
// Kernel 1: partial sums over L.  grid = (B_, LSPLIT), block = 256 threads.
// Measured R3: 43.2us, DRAM 79.9%, 6325 GB/s — at roofline, unchanged.
// ---------------------------------------------------------------------------
__global__ __launch_bounds__(256) void mean_kernel(const float* __restrict__ x) {
    const int b = blockIdx.x;
    const int s = blockIdx.y;
    const int t = threadIdx.x;
    const int rows = L_ / LSPLIT;   // 128

    const float4* xp = (const float4*)(x + ((long long)b * L_ + (long long)s * rows) * D_);
    float4 acc = make_float4(0.f, 0.f, 0.f, 0.f);

#pragma unroll 8
    for (int l = 0; l < rows; ++l) {
        float4 v = xp[(long long)l * D4 + t];
        acc.x += v.x; acc.y += v.y; acc.z += v.z; acc.w += v.w;
    }
    float4* gp = (float4*)g_partial;
    gp[(b * LSPLIT + s) * D4 + t] = acc;
}

// ---------------------------------------------------------------------------
// Kernel 2: normalized query per batch.  grid = B_, block = 256.
// ---------------------------------------------------------------------------
__global__ __launch_bounds__(256) void query_kernel() {
    __shared__ float red_v[256];
    const int b = blockIdx.x;
    const int t = threadIdx.x;

    float4 q = make_float4(0.f, 0.f, 0.f, 0.f);
    const float4* gp = (const float4*)g_partial;
#pragma unroll
    for (int s = 0; s < LSPLIT; ++s) {
        float4 v = gp[(b * LSPLIT + s) * D4 + t];
        q.x += v.x; q.y += v.y; q.z += v.z; q.w += v.w;
    }
    const float invL = 1.0f / (float)L_;
    q.x *= invL; q.y *= invL; q.z *= invL; q.w *= invL;

    red_v[t] = q.x*q.x + q.y*q.y + q.z*q.z + q.w*q.w;
    __syncthreads();
    for (int s = 128; s > 0; s >>= 1) {
        if (t < s) red_v[t] += red_v[t + s];
        __syncthreads();
    }
    const float qinv = 1.0f / fmaxf(sqrtf(red_v[0]), EPS_);
    ((float4*)g_query)[b * D4 + t] =
        make_float4(q.x*qinv, q.y*qinv, q.z*qinv, q.w*qinv);
}

// ---------------------------------------------------------------------------
// Kernel 3: cosine scores.  grid = (PGROUPS, B_) = 512 blocks, 256 thr (8 wp).
// Block (g, b) scores protos [g*64, g*64+64) against batch b's query.
// Full-chip parallelism; 32 batches share each proto group through L2
// (proto set is 4 MiB -> ~128 MiB L2 traffic total, ~12us at the LTS cap).
// ---------------------------------------------------------------------------
__global__ __launch_bounds__(256) void score_part(const float* __restrict__ protos) {
    __shared__ float qs[D_];
    const int g = blockIdx.x;
    const int b = blockIdx.y;
    const int t = threadIdx.x;
    const int lane = t & 31;
    const int wid  = t >> 5;

    ((float4*)qs)[t] = __ldg(&((const float4*)g_query)[b * D4 + t]);
    __syncthreads();

    const float4* q4 = (const float4*)qs;
    // warp w handles protos g*64 + w, +8, ... (8 protos per warp)
    for (int pi = wid; pi < PPG; pi += 8) {
        const int p = g * PPG + pi;
        const float4* pr = (const float4*)(protos + (long long)p * D_);
        float dot = 0.f, sq = 0.f;
#pragma unroll
        for (int j = 0; j < 8; ++j) {
            float4 pv = pr[lane + j * 32];
            float4 qv = q4[lane + j * 32];
            dot += pv.x*qv.x + pv.y*qv.y + pv.z*qv.z + pv.w*qv.w;
            sq  += pv.x*pv.x + pv.y*pv.y + pv.z*pv.z + pv.w*pv.w;
        }
#pragma unroll
        for (int o = 16; o > 0; o >>= 1) {
            dot += __shfl_xor_sync(0xFFFFFFFFu, dot, o);
            sq  += __shfl_xor_sync(0xFFFFFFFFu, sq,  o);
        }
        if (lane == 0)
            g_scores[b * P_ + p] = dot / fmaxf(sqrtf(sq), EPS_);
    }
}

// ---------------------------------------------------------------------------
// Kernel 4: per-batch top-5 + softmax + weighted proto agg.  grid = B_.
// 5 block-parallel argmax passes (lower index wins ties, matching
// lax.top_k; the softmax-weighted aggregate is order-invariant anyway).
// ---------------------------------------------------------------------------
__global__ __launch_bounds__(256) void topk_kernel(const float* __restrict__ protos) {
    __shared__ float scores[P_];
    __shared__ float red_v[256];
    __shared__ int   red_i[256];
    __shared__ float topv[TOPK_];
    __shared__ int   topi[TOPK_];

    const int b = blockIdx.x;
    const int t = threadIdx.x;

#pragma unroll
    for (int j = 0; j < 4; ++j)
        scores[t + j * 256] = __ldg(&g_scores[b * P_ + t + j * 256]);
    __syncthreads();

    for (int k = 0; k < TOPK_; ++k) {
        float bv = -FLT_MAX; int bi = P_;
#pragma unroll
        for (int j = 0; j < 4; ++j) {
            int idx = t + j * 256;
            float v = scores[idx];
            if (v > bv || (v == bv && idx < bi)) { bv = v; bi = idx; }
        }
        red_v[t] = bv; red_i[t] = bi; __syncthreads();
        for (int s = 128; s > 0; s >>= 1) {
            if (t < s) {
                float ov = red_v[t + s]; int oi = red_i[t + s];
                if (ov > red_v[t] || (ov == red_v[t] && oi < red_i[t])) {
                    red_v[t] = ov; red_i[t] = oi;
                }
            }
            __syncthreads();
        }
        if (t == 0) {
            topv[k] = red_v[0];
            topi[k] = red_i[0];
            scores[red_i[0]] = -FLT_MAX;
        }
        __syncthreads();
    }

    // softmax weights (redundant per-thread) folded with ALPHA
    float m = topv[0];
#pragma unroll
    for (int k = 1; k < TOPK_; ++k) m = fmaxf(m, topv[k]);
    float e[TOPK_]; float esum = 0.f;
#pragma unroll
    for (int k = 0; k < TOPK_; ++k) { e[k] = __expf(topv[k] - m); esum += e[k]; }
    const float wsc = ALPHA_ / esum;

    float4 acc = make_float4(0.f, 0.f, 0.f, 0.f);
#pragma unroll
    for (int k = 0; k < TOPK_; ++k) {
        const float4* pr = (const float4*)(protos + (long long)topi[k] * D_);
        float4 pv = pr[t];
        float w = e[k] * wsc;
        acc.x += w * pv.x; acc.y += w * pv.y; acc.z += w * pv.z; acc.w += w * pv.w;
    }
    ((float4*)g_agg)[b * D4 + t] = acc;
}

// ---------------------------------------------------------------------------
// Kernel 5: out = x + agg[b].  Reversed block mapping so first-scheduled
// blocks read the tail of x (still L2-resident from mean_kernel).  Both the
// x loads (.cs, last use) and the out stores (.cs) are streaming/evict-first
// so this 512 MiB stream doesn't flush the reusable tail.  Each block covers
// 1024 consecutive float4 = 4 rows of one batch (never straddles a batch).
// ---------------------------------------------------------------------------
__global__ __launch_bounds__(256) void add_kernel(const float4* __restrict__ x,
                                                  float4* __restrict__ out) {
    const float4* agg = (const float4*)g_agg;
    const int chunk = gridDim.x - 1 - blockIdx.x;
    const int base  = chunk * 1024 + threadIdx.x;
    const int b     = base >> 19;          // batch for all 4 items
    const int d4    = base & (D4 - 1);
    const float4 av = __ldg(&agg[(b << 8) + d4]);
#pragma unroll
    for (int k = 0; k < 4; ++k) {
        const int i = base + k * 256;
        float4 xv = __ldcs(&x[i]);
        xv.x += av.x; xv.y += av.y; xv.z += av.z; xv.w += av.w;
        __stcs(&out[i], xv);
    }
}

// ---------------------------------------------------------------------------
extern "C" void kernel_launch(void* const* d_in, const int* in_sizes, int n_in,
                              void* d_out, int out_size) {
    const float* x      = (const float*)d_in[0];   // [32, 2048, 1024]
    const float* protos = (const float*)d_in[1];   // [1024, 1024]
    float* out          = (float*)d_out;

    dim3 mgrid(B_, LSPLIT);
    mean_kernel<<<mgrid, 256>>>(x);
    query_kernel<<<B_, 256>>>();
    dim3 sgrid(PGROUPS, B_);
    score_part<<<sgrid, 256>>>(protos);
    topk_kernel<<<B_, 256>>>(protos);

    const int total4 = B_ * L_ * D4;               // 16,777,216
    add_kernel<<<total4 / 1024, 256>>>((const float4*)x, (float4*)out);
}